// round 1
// baseline (speedup 1.0000x reference)
#include <cuda_runtime.h>
#include <cuda_bf16.h>
#include <cstdint>

#define N_NODES 100000
#define N_EDGES 3200000
#define IN_DIM  256
#define HIDDEN  128
#define OUT_DIM 64

// ---------------- device scratch (static allocation; no cudaMalloc) ----------------
__device__ __align__(128) float g_h0[(size_t)N_NODES * HIDDEN];   // X @ W1
__device__ __align__(128) float g_h1[(size_t)N_NODES * HIDDEN];   // relu(A @ h0)
__device__ __align__(128) float g_h2[(size_t)N_NODES * OUT_DIM];  // h1 @ W2
__device__ int   g_cnt[N_NODES];
__device__ int   g_row_ptr[N_NODES + 1];
__device__ int   g_cursor[N_NODES];
__device__ __align__(128) int   g_sorted_src[N_EDGES];
__device__ __align__(128) float g_sorted_val[N_EDGES];

// ---------------- CSR build ----------------
__global__ void zero_cnt_kernel() {
    int i = blockIdx.x * blockDim.x + threadIdx.x;
    if (i < N_NODES) g_cnt[i] = 0;
}

__global__ void hist_kernel(const int* __restrict__ edge_dst) {
    int e = blockIdx.x * blockDim.x + threadIdx.x;
    if (e < N_EDGES) atomicAdd(&g_cnt[edge_dst[e]], 1);
}

// single-block chunked exclusive scan of g_cnt -> g_row_ptr (and g_cursor copy)
__global__ void exscan_kernel() {
    __shared__ int sh[1024];
    __shared__ int s_carry;
    if (threadIdx.x == 0) s_carry = 0;
    __syncthreads();
    for (int base = 0; base < N_NODES; base += 1024) {
        int i = base + (int)threadIdx.x;
        int v = (i < N_NODES) ? g_cnt[i] : 0;
        sh[threadIdx.x] = v;
        __syncthreads();
        #pragma unroll
        for (int off = 1; off < 1024; off <<= 1) {
            int t = (threadIdx.x >= off) ? sh[threadIdx.x - off] : 0;
            __syncthreads();
            sh[threadIdx.x] += t;
            __syncthreads();
        }
        int incl = sh[threadIdx.x];
        int carry = s_carry;
        if (i < N_NODES) {
            int ex = carry + incl - v;
            g_row_ptr[i] = ex;
            g_cursor[i]  = ex;
        }
        __syncthreads();
        if (threadIdx.x == 1023) s_carry = carry + incl;
        __syncthreads();
    }
    if (threadIdx.x == 0) g_row_ptr[N_NODES] = s_carry;
}

__global__ void scatter_kernel(const int* __restrict__ edge_src,
                               const int* __restrict__ edge_dst,
                               const float* __restrict__ adj_vals) {
    int e = blockIdx.x * blockDim.x + threadIdx.x;
    if (e >= N_EDGES) return;
    int d = edge_dst[e];
    int pos = atomicAdd(&g_cursor[d], 1);
    g_sorted_src[pos] = edge_src[e];
    g_sorted_val[pos] = adj_vals[e];
}

// ---------------- tiled fp32 GEMM: C[M,Nn] = A[M,K] @ B[K,Nn]; K,Nn multiples of 64 ----------------
__global__ void gemm64_kernel(const float* __restrict__ A, const float* __restrict__ B,
                              float* __restrict__ C, int M, int K, int Nn) {
    __shared__ float As[64][65];   // [m][k], padded
    __shared__ float Bs[64][64];   // [k][n]
    const int tid = threadIdx.x;
    const int tx = tid & 15;       // 16 thread-cols, 4 cols each
    const int ty = tid >> 4;       // 16 thread-rows, 4 rows each
    const int row0 = blockIdx.x * 64;
    const int col0 = blockIdx.y * 64;

    float acc[4][4] = {};

    for (int k0 = 0; k0 < K; k0 += 64) {
        #pragma unroll
        for (int i = 0; i < 16; ++i) {
            int idx = tid + i * 256;
            int m = idx >> 6, k = idx & 63;
            int gr = row0 + m;
            As[m][k] = (gr < M) ? A[(size_t)gr * K + k0 + k] : 0.0f;
        }
        #pragma unroll
        for (int i = 0; i < 16; ++i) {
            int idx = tid + i * 256;
            int k = idx >> 6, n = idx & 63;
            Bs[k][n] = B[(size_t)(k0 + k) * Nn + col0 + n];
        }
        __syncthreads();

        #pragma unroll
        for (int kk = 0; kk < 64; ++kk) {
            float a0 = As[ty * 4 + 0][kk];
            float a1 = As[ty * 4 + 1][kk];
            float a2 = As[ty * 4 + 2][kk];
            float a3 = As[ty * 4 + 3][kk];
            float4 b = *reinterpret_cast<const float4*>(&Bs[kk][tx * 4]);
            acc[0][0] = fmaf(a0, b.x, acc[0][0]); acc[0][1] = fmaf(a0, b.y, acc[0][1]);
            acc[0][2] = fmaf(a0, b.z, acc[0][2]); acc[0][3] = fmaf(a0, b.w, acc[0][3]);
            acc[1][0] = fmaf(a1, b.x, acc[1][0]); acc[1][1] = fmaf(a1, b.y, acc[1][1]);
            acc[1][2] = fmaf(a1, b.z, acc[1][2]); acc[1][3] = fmaf(a1, b.w, acc[1][3]);
            acc[2][0] = fmaf(a2, b.x, acc[2][0]); acc[2][1] = fmaf(a2, b.y, acc[2][1]);
            acc[2][2] = fmaf(a2, b.z, acc[2][2]); acc[2][3] = fmaf(a2, b.w, acc[2][3]);
            acc[3][0] = fmaf(a3, b.x, acc[3][0]); acc[3][1] = fmaf(a3, b.y, acc[3][1]);
            acc[3][2] = fmaf(a3, b.z, acc[3][2]); acc[3][3] = fmaf(a3, b.w, acc[3][3]);
        }
        __syncthreads();
    }

    #pragma unroll
    for (int i = 0; i < 4; ++i) {
        int gr = row0 + ty * 4 + i;
        if (gr < M) {
            float4 o = make_float4(acc[i][0], acc[i][1], acc[i][2], acc[i][3]);
            *reinterpret_cast<float4*>(C + (size_t)gr * Nn + col0 + tx * 4) = o;
        }
    }
}

// ---------------- SpMM (CSR, warp-per-row) ----------------
// layer 1: D=128, fused relu.  lane handles 4 dims (float4).
__global__ void spmm_relu128_kernel(const float* __restrict__ h, float* __restrict__ out) {
    int row = (int)((blockIdx.x * blockDim.x + threadIdx.x) >> 5);
    if (row >= N_NODES) return;
    int lane = threadIdx.x & 31;
    int beg = g_row_ptr[row];
    int end = g_row_ptr[row + 1];
    int c = lane * 4;
    float4 acc = make_float4(0.f, 0.f, 0.f, 0.f);

    int e = beg;
    for (; e + 1 < end; e += 2) {
        int   s0 = __ldg(&g_sorted_src[e]);
        int   s1 = __ldg(&g_sorted_src[e + 1]);
        float v0 = __ldg(&g_sorted_val[e]);
        float v1 = __ldg(&g_sorted_val[e + 1]);
        float4 a = *reinterpret_cast<const float4*>(h + ((size_t)s0 << 7) + c);
        float4 b = *reinterpret_cast<const float4*>(h + ((size_t)s1 << 7) + c);
        acc.x = fmaf(v0, a.x, acc.x); acc.y = fmaf(v0, a.y, acc.y);
        acc.z = fmaf(v0, a.z, acc.z); acc.w = fmaf(v0, a.w, acc.w);
        acc.x = fmaf(v1, b.x, acc.x); acc.y = fmaf(v1, b.y, acc.y);
        acc.z = fmaf(v1, b.z, acc.z); acc.w = fmaf(v1, b.w, acc.w);
    }
    if (e < end) {
        int   s0 = __ldg(&g_sorted_src[e]);
        float v0 = __ldg(&g_sorted_val[e]);
        float4 a = *reinterpret_cast<const float4*>(h + ((size_t)s0 << 7) + c);
        acc.x = fmaf(v0, a.x, acc.x); acc.y = fmaf(v0, a.y, acc.y);
        acc.z = fmaf(v0, a.z, acc.z); acc.w = fmaf(v0, a.w, acc.w);
    }
    float4 r = make_float4(fmaxf(acc.x, 0.f), fmaxf(acc.y, 0.f),
                           fmaxf(acc.z, 0.f), fmaxf(acc.w, 0.f));
    *reinterpret_cast<float4*>(out + ((size_t)row << 7) + c) = r;
}

// layer 2: D=64, identity activation.  lane handles 2 dims (float2).
__global__ void spmm64_kernel(const float* __restrict__ h, float* __restrict__ out) {
    int row = (int)((blockIdx.x * blockDim.x + threadIdx.x) >> 5);
    if (row >= N_NODES) return;
    int lane = threadIdx.x & 31;
    int beg = g_row_ptr[row];
    int end = g_row_ptr[row + 1];
    int c = lane * 2;
    float2 acc = make_float2(0.f, 0.f);

    int e = beg;
    for (; e + 1 < end; e += 2) {
        int   s0 = __ldg(&g_sorted_src[e]);
        int   s1 = __ldg(&g_sorted_src[e + 1]);
        float v0 = __ldg(&g_sorted_val[e]);
        float v1 = __ldg(&g_sorted_val[e + 1]);
        float2 a = *reinterpret_cast<const float2*>(h + ((size_t)s0 << 6) + c);
        float2 b = *reinterpret_cast<const float2*>(h + ((size_t)s1 << 6) + c);
        acc.x = fmaf(v0, a.x, acc.x); acc.y = fmaf(v0, a.y, acc.y);
        acc.x = fmaf(v1, b.x, acc.x); acc.y = fmaf(v1, b.y, acc.y);
    }
    if (e < end) {
        int   s0 = __ldg(&g_sorted_src[e]);
        float v0 = __ldg(&g_sorted_val[e]);
        float2 a = *reinterpret_cast<const float2*>(h + ((size_t)s0 << 6) + c);
        acc.x = fmaf(v0, a.x, acc.x); acc.y = fmaf(v0, a.y, acc.y);
    }
    *reinterpret_cast<float2*>(out + ((size_t)row << 6) + c) = acc;
}

// ---------------- launch ----------------
extern "C" void kernel_launch(void* const* d_in, const int* in_sizes, int n_in,
                              void* d_out, int out_size) {
    const float* x        = (const float*)d_in[0];
    const float* adj_vals = (const float*)d_in[1];
    const float* w1       = (const float*)d_in[2];
    const float* w2       = (const float*)d_in[3];
    const int*   edge_src = (const int*)d_in[4];
    const int*   edge_dst = (const int*)d_in[5];
    float* out = (float*)d_out;

    float *p_h0, *p_h1, *p_h2;
    cudaGetSymbolAddress((void**)&p_h0, g_h0);
    cudaGetSymbolAddress((void**)&p_h1, g_h1);
    cudaGetSymbolAddress((void**)&p_h2, g_h2);

    const int TPB = 256;

    // CSR build (per launch; deterministic row segments, order within row via atomics)
    zero_cnt_kernel<<<(N_NODES + TPB - 1) / TPB, TPB>>>();
    hist_kernel<<<(N_EDGES + TPB - 1) / TPB, TPB>>>(edge_dst);
    exscan_kernel<<<1, 1024>>>();
    scatter_kernel<<<(N_EDGES + TPB - 1) / TPB, TPB>>>(edge_src, edge_dst, adj_vals);

    // layer 1: h0 = X @ W1
    {
        dim3 grid((N_NODES + 63) / 64, HIDDEN / 64);
        gemm64_kernel<<<grid, TPB>>>(x, w1, p_h0, N_NODES, IN_DIM, HIDDEN);
    }
    // h1 = relu(A @ h0)
    spmm_relu128_kernel<<<(N_NODES * 32 + TPB - 1) / TPB, TPB>>>(p_h0, p_h1);

    // layer 2: h2 = h1 @ W2
    {
        dim3 grid((N_NODES + 63) / 64, OUT_DIM / 64);
        gemm64_kernel<<<grid, TPB>>>(p_h1, w2, p_h2, N_NODES, HIDDEN, OUT_DIM);
    }
    // out = A @ h2
    spmm64_kernel<<<(N_NODES * 32 + TPB - 1) / TPB, TPB>>>(p_h2, out);
}

// round 2
// speedup vs baseline: 1.4970x; 1.4970x over previous
#include <cuda_runtime.h>
#include <cuda_bf16.h>
#include <cstdint>

#define N_NODES 100000
#define N_EDGES 3200000
#define IN_DIM  256
#define HIDDEN  128
#define OUT_DIM 64

typedef unsigned long long ull;

// ---------------- device scratch (static; no cudaMalloc) ----------------
__device__ __align__(128) float g_h0[(size_t)N_NODES * HIDDEN];   // X @ W1
__device__ __align__(128) float g_h1[(size_t)N_NODES * HIDDEN];   // relu(A @ h0)
__device__ __align__(128) float g_h2[(size_t)N_NODES * OUT_DIM];  // h1 @ W2
__device__ int  g_cnt[N_NODES];
__device__ int  g_row_ptr[N_NODES + 1];
__device__ int  g_cursor[N_NODES];
__device__ __align__(128) int2 g_edges[N_EDGES];                  // {src, val bits}
#define SCAN_BLOCKS 98
__device__ int  g_bsum[SCAN_BLOCKS];
__device__ int  g_boff[SCAN_BLOCKS];

// ---------------- f32x2 helpers ----------------
__device__ __forceinline__ ull pack2(float x, float y) {
    ull r; asm("mov.b64 %0,{%1,%2};" : "=l"(r) : "f"(x), "f"(y)); return r;
}
__device__ __forceinline__ void ffma2(ull& d, ull a, ull b) {
    asm("fma.rn.f32x2 %0,%1,%2,%0;" : "+l"(d) : "l"(a), "l"(b));
}
__device__ __forceinline__ void unpack2(ull v, float& lo, float& hi) {
    asm("mov.b64 {%0,%1},%2;" : "=f"(lo), "=f"(hi) : "l"(v));
}

// ---------------- CSR build ----------------
__global__ void zero_cnt_kernel() {
    int i = blockIdx.x * blockDim.x + threadIdx.x;
    if (i < N_NODES) g_cnt[i] = 0;
}

__global__ void hist_kernel(const int* __restrict__ edge_dst) {
    int e = blockIdx.x * blockDim.x + threadIdx.x;
    if (e < N_EDGES) atomicAdd(&g_cnt[edge_dst[e]], 1);
}

__device__ __forceinline__ int warp_incl_scan(int v) {
    int lane = threadIdx.x & 31;
    #pragma unroll
    for (int o = 1; o < 32; o <<= 1) {
        int n = __shfl_up_sync(0xffffffffu, v, o);
        if (lane >= o) v += n;
    }
    return v;
}

// stage 1: per-block (1024) reduce -> g_bsum
__global__ void scan_reduce_kernel() {
    int i = blockIdx.x * 1024 + threadIdx.x;
    int v = (i < N_NODES) ? g_cnt[i] : 0;
    #pragma unroll
    for (int o = 16; o > 0; o >>= 1) v += __shfl_down_sync(0xffffffffu, v, o);
    __shared__ int ws[32];
    int wid = threadIdx.x >> 5, lane = threadIdx.x & 31;
    if (lane == 0) ws[wid] = v;
    __syncthreads();
    if (wid == 0) {
        v = ws[lane];
        #pragma unroll
        for (int o = 16; o > 0; o >>= 1) v += __shfl_down_sync(0xffffffffu, v, o);
        if (lane == 0) g_bsum[blockIdx.x] = v;
    }
}

// stage 2: exclusive scan of the 98 partials (1 block, 128 threads)
__global__ void scan_partials_kernel() {
    int t = threadIdx.x;
    int v = (t < SCAN_BLOCKS) ? g_bsum[t] : 0;
    int incl = warp_incl_scan(v);
    __shared__ int ws[4];
    int wid = t >> 5, lane = t & 31;
    if (lane == 31) ws[wid] = incl;
    __syncthreads();
    int off = 0;
    #pragma unroll
    for (int w = 0; w < 4; ++w) if (w < wid) off += ws[w];
    incl += off;
    if (t < SCAN_BLOCKS) g_boff[t] = incl - v;  // exclusive
    if (t == 0) g_row_ptr[N_NODES] = N_EDGES;
}

// stage 3: per-block scan + offset -> row_ptr / cursor
__global__ void scan_final_kernel() {
    int i = blockIdx.x * 1024 + threadIdx.x;
    int v = (i < N_NODES) ? g_cnt[i] : 0;
    int incl = warp_incl_scan(v);
    __shared__ int ws[32];
    int wid = threadIdx.x >> 5, lane = threadIdx.x & 31;
    if (lane == 31) ws[wid] = incl;
    __syncthreads();
    if (wid == 0) { int w = warp_incl_scan(ws[lane]); ws[lane] = w; }
    __syncthreads();
    int off = g_boff[blockIdx.x] + ((wid > 0) ? ws[wid - 1] : 0);
    if (i < N_NODES) {
        int ex = off + incl - v;
        g_row_ptr[i] = ex;
        g_cursor[i]  = ex;
    }
}

__global__ void scatter_kernel(const int* __restrict__ edge_src,
                               const int* __restrict__ edge_dst,
                               const float* __restrict__ adj_vals) {
    int e = blockIdx.x * blockDim.x + threadIdx.x;
    if (e >= N_EDGES) return;
    int d = edge_dst[e];
    int pos = atomicAdd(&g_cursor[d], 1);
    g_edges[pos] = make_int2(edge_src[e], __float_as_int(adj_vals[e]));
}

// ---------------- FFMA2 GEMM: C[M,TN] = A[M,K] @ B[K,TN] ----------------
// tile: 128 rows x TN cols per block; 256 threads; per-thread 8 rows x TN/16 cols.
template<int TK, int TN>
__global__ __launch_bounds__(256, 2)
void gemm_f32x2_kernel(const float* __restrict__ A, const float* __restrict__ B,
                       float* __restrict__ C, int M, int K) {
    constexpr int NCOL = TN / 16;   // cols per thread (8 or 4)
    constexpr int NCP  = NCOL / 2;  // col pairs
    __shared__ float As[128][TK + 4];
    __shared__ float Bs[TK][TN];

    const int t  = threadIdx.x;
    const int tr = t >> 4;          // 0..15 -> rows tr*8..tr*8+7
    const int tc = t & 15;          // 0..15 -> cols tc*NCOL..
    const int row0 = blockIdx.x * 128;

    ull acc[8][NCP];
    #pragma unroll
    for (int r = 0; r < 8; ++r)
        #pragma unroll
        for (int c = 0; c < NCP; ++c) acc[r][c] = 0ull;

    for (int k0 = 0; k0 < K; k0 += TK) {
        // load A tile [128 x TK] (float4 along k)
        constexpr int AF4 = 128 * TK / 4;
        #pragma unroll
        for (int i = 0; i < AF4 / 256; ++i) {
            int idx = t + i * 256;
            int kq = idx % (TK / 4);
            int m  = idx / (TK / 4);
            int gr = row0 + m;
            float4 v = make_float4(0.f, 0.f, 0.f, 0.f);
            if (gr < M) v = *reinterpret_cast<const float4*>(A + (size_t)gr * K + k0 + kq * 4);
            *reinterpret_cast<float4*>(&As[m][kq * 4]) = v;
        }
        // load B tile [TK x TN]
        constexpr int BF4 = TK * TN / 4;
        #pragma unroll
        for (int i = 0; i < BF4 / 256; ++i) {
            int idx = t + i * 256;
            int nq = idx % (TN / 4);
            int kr = idx / (TN / 4);
            *reinterpret_cast<float4*>(&Bs[kr][nq * 4]) =
                *reinterpret_cast<const float4*>(B + (size_t)(k0 + kr) * TN + nq * 4);
        }
        __syncthreads();

        #pragma unroll 4
        for (int kk = 0; kk < TK; ++kk) {
            ull b[NCP];
            #pragma unroll
            for (int c = 0; c < NCP; ++c)
                b[c] = *reinterpret_cast<const ull*>(&Bs[kk][tc * NCOL + 2 * c]);
            #pragma unroll
            for (int r = 0; r < 8; ++r) {
                float a = As[tr * 8 + r][kk];
                ull pa = pack2(a, a);
                #pragma unroll
                for (int c = 0; c < NCP; ++c) ffma2(acc[r][c], pa, b[c]);
            }
        }
        __syncthreads();
    }

    // epilogue
    #pragma unroll
    for (int r = 0; r < 8; ++r) {
        int gr = row0 + tr * 8 + r;
        if (gr >= M) continue;
        #pragma unroll
        for (int q = 0; q < NCOL / 4; ++q) {
            float x0, x1, x2, x3;
            unpack2(acc[r][2 * q + 0], x0, x1);
            unpack2(acc[r][2 * q + 1], x2, x3);
            *reinterpret_cast<float4*>(C + (size_t)gr * TN + tc * NCOL + q * 4) =
                make_float4(x0, x1, x2, x3);
        }
    }
}

// ---------------- SpMM (CSR) ----------------
// layer 1: D=128, warp-per-row, lane = 4 dims, fused relu, 4-edge unroll
__global__ void spmm_relu128_kernel(const float* __restrict__ h, float* __restrict__ out) {
    int row = (int)((blockIdx.x * blockDim.x + threadIdx.x) >> 5);
    if (row >= N_NODES) return;
    int lane = threadIdx.x & 31;
    int beg = g_row_ptr[row];
    int end = g_row_ptr[row + 1];
    int c = lane * 4;
    float4 acc = make_float4(0.f, 0.f, 0.f, 0.f);

    int e = beg;
    int e4 = beg + ((end - beg) & ~3);
    for (; e < e4; e += 4) {
        int2 d0 = __ldg(&g_edges[e + 0]);
        int2 d1 = __ldg(&g_edges[e + 1]);
        int2 d2 = __ldg(&g_edges[e + 2]);
        int2 d3 = __ldg(&g_edges[e + 3]);
        float4 a0 = *reinterpret_cast<const float4*>(h + ((size_t)d0.x << 7) + c);
        float4 a1 = *reinterpret_cast<const float4*>(h + ((size_t)d1.x << 7) + c);
        float4 a2 = *reinterpret_cast<const float4*>(h + ((size_t)d2.x << 7) + c);
        float4 a3 = *reinterpret_cast<const float4*>(h + ((size_t)d3.x << 7) + c);
        float v0 = __int_as_float(d0.y), v1 = __int_as_float(d1.y);
        float v2 = __int_as_float(d2.y), v3 = __int_as_float(d3.y);
        acc.x = fmaf(v0, a0.x, acc.x); acc.y = fmaf(v0, a0.y, acc.y);
        acc.z = fmaf(v0, a0.z, acc.z); acc.w = fmaf(v0, a0.w, acc.w);
        acc.x = fmaf(v1, a1.x, acc.x); acc.y = fmaf(v1, a1.y, acc.y);
        acc.z = fmaf(v1, a1.z, acc.z); acc.w = fmaf(v1, a1.w, acc.w);
        acc.x = fmaf(v2, a2.x, acc.x); acc.y = fmaf(v2, a2.y, acc.y);
        acc.z = fmaf(v2, a2.z, acc.z); acc.w = fmaf(v2, a2.w, acc.w);
        acc.x = fmaf(v3, a3.x, acc.x); acc.y = fmaf(v3, a3.y, acc.y);
        acc.z = fmaf(v3, a3.z, acc.z); acc.w = fmaf(v3, a3.w, acc.w);
    }
    for (; e < end; ++e) {
        int2 d0 = __ldg(&g_edges[e]);
        float v0 = __int_as_float(d0.y);
        float4 a0 = *reinterpret_cast<const float4*>(h + ((size_t)d0.x << 7) + c);
        acc.x = fmaf(v0, a0.x, acc.x); acc.y = fmaf(v0, a0.y, acc.y);
        acc.z = fmaf(v0, a0.z, acc.z); acc.w = fmaf(v0, a0.w, acc.w);
    }
    float4 r = make_float4(fmaxf(acc.x, 0.f), fmaxf(acc.y, 0.f),
                           fmaxf(acc.z, 0.f), fmaxf(acc.w, 0.f));
    *reinterpret_cast<float4*>(out + ((size_t)row << 7) + c) = r;
}

// layer 2: D=64, half-warp per row, lane = 4 dims (float4), 4-edge unroll
__global__ void spmm64_kernel(const float* __restrict__ h, float* __restrict__ out) {
    int gt = blockIdx.x * blockDim.x + threadIdx.x;
    int row = gt >> 4;
    if (row >= N_NODES) return;
    int lane16 = threadIdx.x & 15;
    int beg = g_row_ptr[row];
    int end = g_row_ptr[row + 1];
    int c = lane16 * 4;
    float4 acc = make_float4(0.f, 0.f, 0.f, 0.f);

    int e = beg;
    int e4 = beg + ((end - beg) & ~3);
    for (; e < e4; e += 4) {
        int2 d0 = __ldg(&g_edges[e + 0]);
        int2 d1 = __ldg(&g_edges[e + 1]);
        int2 d2 = __ldg(&g_edges[e + 2]);
        int2 d3 = __ldg(&g_edges[e + 3]);
        float4 a0 = *reinterpret_cast<const float4*>(h + ((size_t)d0.x << 6) + c);
        float4 a1 = *reinterpret_cast<const float4*>(h + ((size_t)d1.x << 6) + c);
        float4 a2 = *reinterpret_cast<const float4*>(h + ((size_t)d2.x << 6) + c);
        float4 a3 = *reinterpret_cast<const float4*>(h + ((size_t)d3.x << 6) + c);
        float v0 = __int_as_float(d0.y), v1 = __int_as_float(d1.y);
        float v2 = __int_as_float(d2.y), v3 = __int_as_float(d3.y);
        acc.x = fmaf(v0, a0.x, acc.x); acc.y = fmaf(v0, a0.y, acc.y);
        acc.z = fmaf(v0, a0.z, acc.z); acc.w = fmaf(v0, a0.w, acc.w);
        acc.x = fmaf(v1, a1.x, acc.x); acc.y = fmaf(v1, a1.y, acc.y);
        acc.z = fmaf(v1, a1.z, acc.z); acc.w = fmaf(v1, a1.w, acc.w);
        acc.x = fmaf(v2, a2.x, acc.x); acc.y = fmaf(v2, a2.y, acc.y);
        acc.z = fmaf(v2, a2.z, acc.z); acc.w = fmaf(v2, a2.w, acc.w);
        acc.x = fmaf(v3, a3.x, acc.x); acc.y = fmaf(v3, a3.y, acc.y);
        acc.z = fmaf(v3, a3.z, acc.z); acc.w = fmaf(v3, a3.w, acc.w);
    }
    for (; e < end; ++e) {
        int2 d0 = __ldg(&g_edges[e]);
        float v0 = __int_as_float(d0.y);
        float4 a0 = *reinterpret_cast<const float4*>(h + ((size_t)d0.x << 6) + c);
        acc.x = fmaf(v0, a0.x, acc.x); acc.y = fmaf(v0, a0.y, acc.y);
        acc.z = fmaf(v0, a0.z, acc.z); acc.w = fmaf(v0, a0.w, acc.w);
    }
    *reinterpret_cast<float4*>(out + ((size_t)row << 6) + c) = acc;
}

// ---------------- launch ----------------
extern "C" void kernel_launch(void* const* d_in, const int* in_sizes, int n_in,
                              void* d_out, int out_size) {
    const float* x        = (const float*)d_in[0];
    const float* adj_vals = (const float*)d_in[1];
    const float* w1       = (const float*)d_in[2];
    const float* w2       = (const float*)d_in[3];
    const int*   edge_src = (const int*)d_in[4];
    const int*   edge_dst = (const int*)d_in[5];
    float* out = (float*)d_out;

    float *p_h0, *p_h1, *p_h2;
    cudaGetSymbolAddress((void**)&p_h0, g_h0);
    cudaGetSymbolAddress((void**)&p_h1, g_h1);
    cudaGetSymbolAddress((void**)&p_h2, g_h2);

    const int TPB = 256;

    // CSR build
    zero_cnt_kernel<<<(N_NODES + TPB - 1) / TPB, TPB>>>();
    hist_kernel<<<(N_EDGES + TPB - 1) / TPB, TPB>>>(edge_dst);
    scan_reduce_kernel<<<SCAN_BLOCKS, 1024>>>();
    scan_partials_kernel<<<1, 128>>>();
    scan_final_kernel<<<SCAN_BLOCKS, 1024>>>();
    scatter_kernel<<<(N_EDGES + TPB - 1) / TPB, TPB>>>(edge_src, edge_dst, adj_vals);

    // layer 1: h0 = X @ W1 (K=256, N=128)
    gemm_f32x2_kernel<32, HIDDEN><<<(N_NODES + 127) / 128, 256>>>(x, w1, p_h0, N_NODES, IN_DIM);
    // h1 = relu(A @ h0)
    spmm_relu128_kernel<<<(N_NODES * 32 + TPB - 1) / TPB, TPB>>>(p_h0, p_h1);
    // layer 2: h2 = h1 @ W2 (K=128, N=64)
    gemm_f32x2_kernel<32, OUT_DIM><<<(N_NODES + 127) / 128, 256>>>(p_h1, w2, p_h2, N_NODES, HIDDEN);
    // out = A @ h2
    spmm64_kernel<<<(N_NODES * 16 + TPB - 1) / TPB, TPB>>>(p_h2, out);
}